// round 14
// baseline (speedup 1.0000x reference)
#include <cuda_runtime.h>
#include <cuda_bf16.h>
#include <cstdint>

#define Bn 4
#define Cn 64
#define On 64
#define Hn 128
#define Wn 128
#define KK 9
#define NPIX (Bn * Hn * Wn)

// Scratch (device globals: no allocation allowed)
__device__ __align__(16) float g_xT[(size_t)Bn * Hn * Wn * Cn];  // x in NHWC
__device__ __align__(16) float g_off[18 * NPIX];                 // offsets [ch][pix]
__device__ __align__(16) unsigned short g_wbf[KK * 2 * Cn * On]; // per tap: swizzled hi tile then lo tile

// ---------------- helpers ----------------
__device__ __forceinline__ uint32_t smem_u32(const void* p) {
    uint32_t a;
    asm("{ .reg .u64 t; cvta.to.shared.u64 t, %1; cvt.u32.u64 %0, t; }" : "=r"(a) : "l"(p));
    return a;
}
__device__ __forceinline__ uint32_t bf16x2_of(float lo, float hi) {
    uint32_t r;
    asm("cvt.rn.bf16x2.f32 %0, %1, %2;" : "=r"(r) : "f"(hi), "f"(lo));
    return r;
}
__device__ __forceinline__ void ldm_x4(uint32_t* r, uint32_t addr) {
    asm volatile("ldmatrix.sync.aligned.m8n8.x4.shared.b16 {%0,%1,%2,%3}, [%4];"
                 : "=r"(r[0]), "=r"(r[1]), "=r"(r[2]), "=r"(r[3]) : "r"(addr));
}
__device__ __forceinline__ void mma_bf16(float4& d, const uint32_t* a, uint32_t b0, uint32_t b1) {
    asm volatile(
        "mma.sync.aligned.m16n8k16.row.col.f32.bf16.bf16.f32 "
        "{%0,%1,%2,%3}, {%4,%5,%6,%7}, {%8,%9}, {%0,%1,%2,%3};"
        : "+f"(d.x), "+f"(d.y), "+f"(d.z), "+f"(d.w)
        : "r"(a[0]), "r"(a[1]), "r"(a[2]), "r"(a[3]), "r"(b0), "r"(b1));
}
__device__ __forceinline__ void mbar_init(uint32_t a, uint32_t cnt) {
    asm volatile("mbarrier.init.shared.b64 [%0], %1;" :: "r"(a), "r"(cnt) : "memory");
}
__device__ __forceinline__ void mbar_inval(uint32_t a) {
    asm volatile("mbarrier.inval.shared.b64 [%0];" :: "r"(a) : "memory");
}
__device__ __forceinline__ void mbar_arrive(uint32_t a) {
    asm volatile("mbarrier.arrive.shared.b64 _, [%0];" :: "r"(a) : "memory");
}
__device__ __forceinline__ void mbar_wait(uint32_t a, uint32_t parity) {
    uint32_t done;
    asm volatile(
        "{\n\t.reg .pred p;\n\t"
        "mbarrier.try_wait.parity.acquire.cta.shared::cta.b64 p, [%1], %2;\n\t"
        "selp.b32 %0, 1, 0, p;\n\t}"
        : "=r"(done) : "r"(a), "r"(parity) : "memory");
    if (!done) {
        asm volatile(
            "{\n\t.reg .pred P1;\n\t"
            "WL_%=:\n\t"
            "mbarrier.try_wait.parity.acquire.cta.shared::cta.b64 P1, [%0], %1, 0x989680;\n\t"
            "@P1 bra.uni WD_%=;\n\t"
            "bra.uni WL_%=;\n\t"
            "WD_%=:\n\t}"
            :: "r"(a), "r"(parity) : "memory");
    }
}
__device__ __forceinline__ unsigned long long pack2(float lo, float hi) {
    unsigned long long r;
    asm("mov.b64 %0, {%1,%2};" : "=l"(r) : "f"(lo), "f"(hi));
    return r;
}
__device__ __forceinline__ unsigned long long pack1(float a) { return pack2(a, a); }
__device__ __forceinline__ void ffma2(unsigned long long& d, unsigned long long a, unsigned long long b) {
    asm("fma.rn.f32x2 %0, %1, %2, %0;" : "+l"(d) : "l"(a), "l"(b));
}
__device__ __forceinline__ float2 unpk2(unsigned long long v) {
    float2 r;
    asm("mov.b64 {%0,%1}, %2;" : "=f"(r.x), "=f"(r.y) : "l"(v));
    return r;
}

// ---------------------------------------------------------------------------
// Kernel 1: NCHW -> NHWC transpose of x
// ---------------------------------------------------------------------------
__global__ void transpose_k(const float* __restrict__ x) {
    __shared__ float tile[32][33];
    int w0 = blockIdx.x * 32;
    int c0 = blockIdx.y * 32;
    int bh = blockIdx.z;
    int b = bh >> 7, h = bh & 127;
    int tx = threadIdx.x, ty = threadIdx.y;
#pragma unroll
    for (int i = 0; i < 4; i++) {
        int c = c0 + ty + i * 8;
        tile[ty + i * 8][tx] = x[(((size_t)b * Cn + c) * Hn + h) * Wn + (w0 + tx)];
    }
    __syncthreads();
#pragma unroll
    for (int i = 0; i < 4; i++) {
        int w = w0 + ty + i * 8;
        g_xT[(((size_t)b * Hn + h) * Wn + w) * Cn + (c0 + tx)] = tile[tx][ty + i * 8];
    }
}

// ---------------------------------------------------------------------------
// Kernel 2: weight (O,C,3,3) -> per-tap bf16 hi/lo swizzled B tiles.
// ---------------------------------------------------------------------------
__global__ void prep_wbf(const float* __restrict__ weight) {
    int d = blockIdx.x * 256 + threadIdx.x;
    if (d >= KK * Cn * On) return;
    int k = d >> 12;
    int rem = d & 4095;
    int c = rem >> 6;
    int o = rem & 63;
    float f = weight[(o * Cn + c) * KK + k];
    __nv_bfloat16 h = __float2bfloat16(f);
    float hf = __bfloat162float(h);
    __nv_bfloat16 l = __float2bfloat16(f - hf);
    uint32_t off = (uint32_t)o * 128 + (uint32_t)c * 2;
    uint32_t sw = off ^ ((off >> 3) & 0x70);
    g_wbf[(size_t)k * 8192 + (sw >> 1)] = __bfloat16_as_ushort(h);
    g_wbf[(size_t)k * 8192 + 4096 + (sw >> 1)] = __bfloat16_as_ushort(l);
}

// ---------------------------------------------------------------------------
// Kernel 3: offset conv (unchanged from R12)
// ---------------------------------------------------------------------------
__global__ __launch_bounds__(256) void offset_conv_k(
    const float* __restrict__ x,
    const float* __restrict__ offset_w,
    const float* __restrict__ offset_b)
{
    __shared__ float wS[KK * Cn * 20];

    int tid = threadIdx.x;
    for (int s = tid; s < KK * Cn * 18; s += 256) {
        int j = s % 18;
        int t2 = s / 18;
        int c = t2 & 63;
        int tap = t2 >> 6;
        wS[t2 * 20 + j] = offset_w[(j * Cn + c) * KK + tap];
    }
    __syncthreads();

    int pid = blockIdx.x * 256 + tid;
    int b = pid >> 14;
    int y = (pid >> 7) & 127;
    int xw = pid & 127;

    unsigned long long acc[9];
#pragma unroll
    for (int j = 0; j < 9; j++) acc[j] = pack2(offset_b[2 * j], offset_b[2 * j + 1]);

    const float* xbase = x + (size_t)b * Cn * Hn * Wn;

    for (int ky = 0; ky < 3; ky++) {
        int yy = y - 1 + ky;
        if (yy < 0 || yy >= Hn) continue;
        for (int kx = 0; kx < 3; kx++) {
            int xx = xw - 1 + kx;
            if (xx < 0 || xx >= Wn) continue;
            int tap = ky * 3 + kx;
            const float* xc = xbase + yy * Wn + xx;
            const float* wrow = wS + tap * Cn * 20;
#pragma unroll 4
            for (int c = 0; c < Cn; c++) {
                float a = __ldg(xc + (size_t)c * (Hn * Wn));
                unsigned long long ap = pack1(a);
                const float* wr = wrow + c * 20;
                ulonglong2 w01 = *(const ulonglong2*)(wr);
                ulonglong2 w23 = *(const ulonglong2*)(wr + 4);
                ulonglong2 w45 = *(const ulonglong2*)(wr + 8);
                ulonglong2 w67 = *(const ulonglong2*)(wr + 12);
                unsigned long long w8 = *(const unsigned long long*)(wr + 16);
                ffma2(acc[0], ap, w01.x);
                ffma2(acc[1], ap, w01.y);
                ffma2(acc[2], ap, w23.x);
                ffma2(acc[3], ap, w23.y);
                ffma2(acc[4], ap, w45.x);
                ffma2(acc[5], ap, w45.y);
                ffma2(acc[6], ap, w67.x);
                ffma2(acc[7], ap, w67.y);
                ffma2(acc[8], ap, w8);
            }
        }
    }

#pragma unroll
    for (int j = 0; j < 9; j++) {
        float2 v = unpk2(acc[j]);
        g_off[(2 * j) * NPIX + pid] = v.x;
        g_off[(2 * j + 1) * NPIX + pid] = v.y;
    }
}

// ---------------------------------------------------------------------------
// Kernel 4: warp-specialized deformable conv (mma.sync bf16 hi/lo).
// CTA = 128 px (16w x 8h) x 64 o, 256 threads.
// Warps 0-3 produce (gather + split + B staging), warps 4-7 consume (MMA).
// Double-buffered stages, mbarrier full/empty handshake.
// Stage layout: [A_hi 16K][A_lo 16K][B_hi 8K][B_lo 8K] = 48K; 2 stages.
// ---------------------------------------------------------------------------
#define TS_W 16
#define TS_H 8
#define STG_SZ 49152
#define SM_ST(s) (1024 + (s) * STG_SZ)
#define SM_TOTAL (1024 + 2 * STG_SZ)   // 99328 B

__global__ __launch_bounds__(256, 2) void deform_k(
    const float* __restrict__ bias,
    float* __restrict__ out)
{
    extern __shared__ char dsm[];
    uint32_t smem_base = smem_u32(dsm);
    uint32_t mb_full0 = smem_base + 0;
    uint32_t mb_full1 = smem_base + 8;
    uint32_t mb_empty0 = smem_base + 16;
    uint32_t mb_empty1 = smem_base + 24;

    int tid = threadIdx.x;
    int wid = tid >> 5;
    int lane = tid & 31;
    int x0t = blockIdx.x * TS_W;
    int y0t = blockIdx.y * TS_H;
    int b = blockIdx.z;

    if (tid == 0) {
        mbar_init(mb_full0, 128);
        mbar_init(mb_full1, 128);
        mbar_init(mb_empty0, 128);
        mbar_init(mb_empty1, 128);
    }
    __syncthreads();

    const bool producer = (wid < 4);

    if (producer) {
        // ---- PRODUCER: 128 threads; 16 lanes per pixel, 8 px/pass, 16 passes
        int ptid = tid;                  // 0..127
        int gchunk = ptid & 15;
        int slot = ptid >> 4;            // 0..7
        int cc = gchunk * 4;
        const float* xb = g_xT + (size_t)b * Hn * Wn * Cn;

        for (int k = 0; k < KK; k++) {
            int s = k & 1, u = k >> 1;
            uint32_t mbE = s ? mb_empty1 : mb_empty0;
            uint32_t mbF = s ? mb_full1 : mb_full0;
            if (k >= 2) mbar_wait(mbE, (u - 1) & 1);

            char* stg = dsm + SM_ST(s);

            // stage B hi/lo (16 KB)
            {
                const float4* src = (const float4*)(g_wbf + (size_t)k * 8192);
                float4* dst = (float4*)(stg + 32768);
#pragma unroll
                for (int r = 0; r < 8; r++) dst[ptid + r * 128] = src[ptid + r * 128];
            }

            // gather + split
            int ky = k / 3, kx = k - ky * 3;
#pragma unroll 4
            for (int pass = 0; pass < 16; pass++) {
                int p = pass * 8 + slot;
                int lw = p & 15, lh = p >> 4;
                int gx = x0t + lw, gy = y0t + lh;
                int gpix = (b * Hn + gy) * Wn + gx;
                float offY = __ldg(g_off + (2 * k) * NPIX + gpix);
                float offX = __ldg(g_off + (2 * k + 1) * NPIX + gpix);
                float pfy = (float)(gy - 1 + ky) + offY;
                float pfx = (float)(gx - 1 + kx) + offX;
                float fy0 = floorf(pfy), fx0 = floorf(pfx);
                float wy1 = pfy - fy0, wx1 = pfx - fx0;
                float wy0 = 1.f - wy1, wx0 = 1.f - wx1;
                int iy0 = (int)fy0, ix0 = (int)fx0;
                int iy1 = iy0 + 1, ix1 = ix0 + 1;
                bool vy0 = (iy0 >= 0) & (iy0 < Hn);
                bool vy1 = (iy1 >= 0) & (iy1 < Hn);
                bool vx0 = (ix0 >= 0) & (ix0 < Wn);
                bool vx1 = (ix1 >= 0) & (ix1 < Wn);
                int cy0 = min(max(iy0, 0), Hn - 1);
                int cy1 = min(max(iy1, 0), Hn - 1);
                int cx0 = min(max(ix0, 0), Wn - 1);
                int cx1 = min(max(ix1, 0), Wn - 1);

                const float* bp = xb + cc;
                float4 r = make_float4(0.f, 0.f, 0.f, 0.f);
                if (vy0 & vx0) {
                    float4 t = *(const float4*)(bp + (cy0 * Wn + cx0) * Cn);
                    float w = wy0 * wx0;
                    r.x += w * t.x; r.y += w * t.y; r.z += w * t.z; r.w += w * t.w;
                }
                if (vy0 & vx1) {
                    float4 t = *(const float4*)(bp + (cy0 * Wn + cx1) * Cn);
                    float w = wy0 * wx1;
                    r.x += w * t.x; r.y += w * t.y; r.z += w * t.z; r.w += w * t.w;
                }
                if (vy1 & vx0) {
                    float4 t = *(const float4*)(bp + (cy1 * Wn + cx0) * Cn);
                    float w = wy1 * wx0;
                    r.x += w * t.x; r.y += w * t.y; r.z += w * t.z; r.w += w * t.w;
                }
                if (vy1 & vx1) {
                    float4 t = *(const float4*)(bp + (cy1 * Wn + cx1) * Cn);
                    float w = wy1 * wx1;
                    r.x += w * t.x; r.y += w * t.y; r.z += w * t.z; r.w += w * t.w;
                }

                uint32_t hi0 = bf16x2_of(r.x, r.y);
                uint32_t hi1 = bf16x2_of(r.z, r.w);
                float b0 = __uint_as_float(hi0 << 16);
                float b1 = __uint_as_float(hi0 & 0xFFFF0000u);
                float b2 = __uint_as_float(hi1 << 16);
                float b3 = __uint_as_float(hi1 & 0xFFFF0000u);
                uint32_t lo0 = bf16x2_of(r.x - b0, r.y - b1);
                uint32_t lo1 = bf16x2_of(r.z - b2, r.w - b3);

                uint32_t off = (uint32_t)p * 128 + (uint32_t)cc * 2;
                uint32_t sw = off ^ ((off >> 3) & 0x70);
                *(uint2*)(stg + sw) = make_uint2(hi0, hi1);
                *(uint2*)(stg + 16384 + sw) = make_uint2(lo0, lo1);
            }

            mbar_arrive(mbF);
        }
    } else {
        // ---- CONSUMER: warps 4-7; warp cw handles px [cw*32, cw*32+32) x 64 o
        int cw = wid - 4;
        uint32_t xorv = (uint32_t)(lane & 7) << 4;
        int arow = (lane & 7) + ((lane >> 3) & 1) * 8;
        int acol16 = (lane >> 4) * 16;
        int brow = ((lane >> 4) * 8) + (lane & 7);
        int bcol16 = ((lane >> 3) & 1) * 16;

        float4 dacc[2][8];
#pragma unroll
        for (int t = 0; t < 2; t++)
#pragma unroll
            for (int j = 0; j < 8; j++) dacc[t][j] = make_float4(0.f, 0.f, 0.f, 0.f);

        for (int k = 0; k < KK; k++) {
            int s = k & 1, u = k >> 1;
            uint32_t mbF = s ? mb_full1 : mb_full0;
            uint32_t mbE = s ? mb_empty1 : mb_empty0;
            mbar_wait(mbF, u & 1);

            uint32_t stg = smem_base + SM_ST(s);
#pragma unroll
            for (int ks = 0; ks < 4; ks++) {
                uint32_t a0off = (uint32_t)((cw * 32 + arow) * 128 + ks * 32 + acol16) ^ xorv;
                uint32_t a1off = (uint32_t)((cw * 32 + 16 + arow) * 128 + ks * 32 + acol16) ^ xorv;
                uint32_t ah0[4], al0[4], ah1[4], al1[4];
                ldm_x4(ah0, stg + a0off);
                ldm_x4(al0, stg + 16384 + a0off);
                ldm_x4(ah1, stg + a1off);
                ldm_x4(al1, stg + 16384 + a1off);
#pragma unroll
                for (int jj = 0; jj < 4; jj++) {
                    uint32_t boff = (uint32_t)((16 * jj + brow) * 128 + ks * 32 + bcol16) ^ xorv;
                    uint32_t bh[4], bl[4];
                    ldm_x4(bh, stg + 32768 + boff);
                    ldm_x4(bl, stg + 40960 + boff);
                    mma_bf16(dacc[0][2 * jj],     ah0, bh[0], bh[1]);
                    mma_bf16(dacc[0][2 * jj + 1], ah0, bh[2], bh[3]);
                    mma_bf16(dacc[0][2 * jj],     al0, bh[0], bh[1]);
                    mma_bf16(dacc[0][2 * jj + 1], al0, bh[2], bh[3]);
                    mma_bf16(dacc[0][2 * jj],     ah0, bl[0], bl[1]);
                    mma_bf16(dacc[0][2 * jj + 1], ah0, bl[2], bl[3]);
                    mma_bf16(dacc[1][2 * jj],     ah1, bh[0], bh[1]);
                    mma_bf16(dacc[1][2 * jj + 1], ah1, bh[2], bh[3]);
                    mma_bf16(dacc[1][2 * jj],     al1, bh[0], bh[1]);
                    mma_bf16(dacc[1][2 * jj + 1], al1, bh[2], bh[3]);
                    mma_bf16(dacc[1][2 * jj],     ah1, bl[0], bl[1]);
                    mma_bf16(dacc[1][2 * jj + 1], ah1, bl[2], bl[3]);
                }
            }

            mbar_arrive(mbE);
        }

        // stash accumulators in registers until after the convergence barrier
        // (written to sD below)
        __syncthreads();   // (1) all ldmatrix done everywhere; producers idle here

        float* sD = (float*)(dsm + SM_ST(0));
        int r0 = cw * 32 + (lane >> 2);
#pragma unroll
        for (int t = 0; t < 2; t++) {
            int rt0 = r0 + t * 16;
            int rt1 = rt0 + 8;
#pragma unroll
            for (int j = 0; j < 8; j++) {
                int col = j * 8 + (lane & 3) * 2;
                sD[col * 128 + rt0] = dacc[t][j].x;
                sD[(col + 1) * 128 + rt0] = dacc[t][j].y;
                sD[col * 128 + rt1] = dacc[t][j].z;
                sD[(col + 1) * 128 + rt1] = dacc[t][j].w;
            }
        }
    }

    if (producer) __syncthreads();   // (1) producers meet consumers here

    __syncthreads();                 // (2) sD complete

    // all 256 threads: coalesced NCHW stores
    float* sD = (float*)(dsm + SM_ST(0));
#pragma unroll
    for (int r = 0; r < 32; r++) {
        int i = r * 256 + tid;           // 0..8191
        int o = i >> 5;                  // wrong? no: 8192/256... o = i>>7
        (void)o;
    }
#pragma unroll
    for (int r = 0; r < 32; r++) {
        int i = r * 256 + tid;           // 0..8191
        int o = i >> 7;
        int p = i & 127;
        int lw = p & 15, lh = p >> 4;
        float v = sD[o * 128 + p] + __ldg(bias + o);
        out[(((size_t)b * On + o) * Hn + (y0t + lh)) * Wn + (x0t + lw)] = v;
    }

    __syncthreads();
    if (tid == 0) {
        mbar_inval(mb_full0);
        mbar_inval(mb_full1);
        mbar_inval(mb_empty0);
        mbar_inval(mb_empty1);
    }
}

// ---------------------------------------------------------------------------
extern "C" void kernel_launch(void* const* d_in, const int* in_sizes, int n_in,
                              void* d_out, int out_size) {
    const float* x        = (const float*)d_in[0];   // (4,64,128,128)
    const float* offset_w = (const float*)d_in[1];   // (18,64,3,3)
    const float* offset_b = (const float*)d_in[2];   // (18,)
    const float* weight   = (const float*)d_in[3];   // (64,64,3,3)
    const float* bias     = (const float*)d_in[4];   // (64,)
    float* out = (float*)d_out;                      // (4,64,128,128)

    cudaFuncSetAttribute(deform_k, cudaFuncAttributeMaxDynamicSharedMemorySize, SM_TOTAL);

    transpose_k<<<dim3(Wn / 32, Cn / 32, Bn * Hn), dim3(32, 8)>>>(x);
    prep_wbf<<<(KK * Cn * On + 255) / 256, 256>>>(weight);
    offset_conv_k<<<NPIX / 256, 256>>>(x, offset_w, offset_b);
    deform_k<<<dim3(Wn / TS_W, Hn / TS_H, Bn), 256, SM_TOTAL>>>(bias, out);
}